// round 7
// baseline (speedup 1.0000x reference)
#include <cuda_runtime.h>
#include <cstdint>

// BinStats_27401891348536: x [64,512,28,28] f32; bin_edges [512,11];
// feature_ranges [512]; bin_counts [512,10]; out = bin_counts + histogram.
#define C_         512
#define NB_        10
#define NEDGE_     11
#define ROWBYTES_  3136                 // 784 floats
#define TROWS_     16                   // rows per tile (contiguous in gmem)
#define TILEBYTES_ (TROWS_ * ROWBYTES_) // 50176
#define NTILES_    2048                 // 32768 rows / 16
#define GRID_      128                  // tile stride; 16*128 = 2048 ≡ 0 mod 512
#define TPB_       (NTILES_ / GRID_)    // 16 tiles per block
#define NSTAGE_    3
#define CWARPS_    16
#define THREADS_   (32 * (CWARPS_ + 1)) // 544
#define SMEM_DATA_ 1024
#define SMEM_TOTAL_ (SMEM_DATA_ + NSTAGE_ * TILEBYTES_)

__global__ void init_out_kernel(const float* __restrict__ bc,
                                float* __restrict__ out, int n) {
    int i = blockIdx.x * blockDim.x + threadIdx.x;
    if (i < n) out[i] = bc[i];
}

// ---- mbarrier helpers ----
__device__ __forceinline__ uint32_t smem_u32(const void* p) {
    return (uint32_t)__cvta_generic_to_shared(p);
}
__device__ __forceinline__ void mbar_init(uint32_t a, uint32_t cnt) {
    asm volatile("mbarrier.init.shared.b64 [%0], %1;" :: "r"(a), "r"(cnt) : "memory");
}
__device__ __forceinline__ void mbar_expect_tx(uint32_t a, uint32_t bytes) {
    asm volatile("mbarrier.arrive.expect_tx.shared.b64 _, [%0], %1;"
                 :: "r"(a), "r"(bytes) : "memory");
}
__device__ __forceinline__ void mbar_arrive(uint32_t a) {
    asm volatile("mbarrier.arrive.shared.b64 _, [%0];" :: "r"(a) : "memory");
}
__device__ __forceinline__ void mbar_wait(uint32_t a, uint32_t parity) {
    asm volatile(
        "{\n\t.reg .pred P;\n\t"
        "WAIT_%=: mbarrier.try_wait.parity.acquire.cta.shared::cta.b64 P, [%0], %1, 0x989680;\n\t"
        "@P bra.uni DONE_%=;\n\t"
        "bra.uni WAIT_%=;\n\t"
        "DONE_%=:\n\t}"
        :: "r"(a), "r"(parity) : "memory");
}
__device__ __forceinline__ void bulk_copy(uint32_t dst, const void* src,
                                          uint32_t bytes, uint32_t mbar) {
    asm volatile(
        "cp.async.bulk.shared::cta.global.mbarrier::complete_tx::bytes [%0], [%1], %2, [%3];"
        :: "r"(dst), "l"(src), "r"(bytes), "r"(mbar) : "memory");
}

// Proven binning (rel_err 8.4e-6 in R2-R5):
// searchsorted(inner,'left') uniform edges: b = clamp(ceil((x - s0)/D), 0, 9).
__device__ __forceinline__ unsigned long long bump(float x, float invD, float c0) {
    float u = fmaf(x, invD, c0);
    u = fminf(fmaxf(u, 0.0f), 9.0f);
    int b = __float2int_ru(u);
    return 1ULL << (6 * b);
}

__global__ void __launch_bounds__(THREADS_, 1) hist_kernel(
    const float* __restrict__ x,
    const float* __restrict__ bin_edges,
    const float* __restrict__ fr,
    float*       __restrict__ out)
{
    extern __shared__ char smem[];
    const int tid = threadIdx.x, wid = tid >> 5, lane = tid & 31;
    const uint32_t sbase = smem_u32(smem);
    auto fullb  = [&](int s) { return sbase + s * 8u; };
    auto emptyb = [&](int s) { return sbase + 64u + s * 8u; };

    if (tid == 0) {
#pragma unroll
        for (int s = 0; s < NSTAGE_; s++) {
            mbar_init(fullb(s), 1);
            mbar_init(emptyb(s), CWARPS_);
        }
    }
    __syncthreads();

    if (wid == CWARPS_) {
        // -------- producer warp --------
        if (lane == 0) {
            int stage = 0, phase = 1;      // first empty-wait passes immediately
            for (int i = 0; i < TPB_; i++) {
                const int t = blockIdx.x + i * GRID_;
                mbar_wait(emptyb(stage), phase);
                mbar_expect_tx(fullb(stage), TILEBYTES_);
                bulk_copy(sbase + SMEM_DATA_ + stage * TILEBYTES_,
                          (const char*)x + (size_t)t * TILEBYTES_,
                          TILEBYTES_, fullb(stage));
                if (++stage == NSTAGE_) { stage = 0; phase ^= 1; }
            }
        }
        return;
    }

    // -------- consumer warp: row `wid` of every tile; channel constant --------
    const int c = ((blockIdx.x * TROWS_) + wid) & (C_ - 1);
    const float range = __ldg(&fr[c]);
    const float s0 = __ldg(&bin_edges[c * NEDGE_ + 1]) * range;
    const float s8 = __ldg(&bin_edges[c * NEDGE_ + 9]) * range;
    const float invD = 8.0f / (s8 - s0);
    const float c0   = -s0 * invD;
    const bool tail = (lane < 4);

    unsigned long long a0 = 0, a1 = 0, a2 = 0, a3 = 0;
    unsigned cnt[NB_];
#pragma unroll
    for (int b = 0; b < NB_; b++) cnt[b] = 0;

    int stage = 0, phase = 0;
    for (int i = 0; i < TPB_; i++) {
        mbar_wait(fullb(stage), phase);
        const float4* p = (const float4*)(smem + SMEM_DATA_
                                          + stage * TILEBYTES_ + wid * ROWBYTES_);
        float4 v0 = p[  0 + lane];
        float4 v1 = p[ 32 + lane];
        float4 v2 = p[ 64 + lane];
        float4 v3 = p[ 96 + lane];
        float4 v4 = p[128 + lane];
        float4 v5 = p[160 + lane];
        float4 vt;
        if (tail) vt = p[192 + lane];

        a0 += bump(v0.x, invD, c0); a1 += bump(v0.y, invD, c0);
        a2 += bump(v0.z, invD, c0); a3 += bump(v0.w, invD, c0);
        a0 += bump(v1.x, invD, c0); a1 += bump(v1.y, invD, c0);
        a2 += bump(v1.z, invD, c0); a3 += bump(v1.w, invD, c0);
        a0 += bump(v2.x, invD, c0); a1 += bump(v2.y, invD, c0);
        a2 += bump(v2.z, invD, c0); a3 += bump(v2.w, invD, c0);
        a0 += bump(v3.x, invD, c0); a1 += bump(v3.y, invD, c0);
        a2 += bump(v3.z, invD, c0); a3 += bump(v3.w, invD, c0);
        a0 += bump(v4.x, invD, c0); a1 += bump(v4.y, invD, c0);
        a2 += bump(v4.z, invD, c0); a3 += bump(v4.w, invD, c0);
        a0 += bump(v5.x, invD, c0); a1 += bump(v5.y, invD, c0);
        a2 += bump(v5.z, invD, c0); a3 += bump(v5.w, invD, c0);
        if (tail) {
            a0 += bump(vt.x, invD, c0); a1 += bump(vt.y, invD, c0);
            a2 += bump(vt.z, invD, c0); a3 += bump(vt.w, invD, c0);
        }

        if (lane == 0) mbar_arrive(emptyb(stage));
        if (++stage == NSTAGE_) { stage = 0; phase ^= 1; }

        if ((i & 7) == 7) {                     // every 8 tiles: <=56 < 63 per field
#pragma unroll
            for (int b = 0; b < NB_; b++) {
                const int sh = 6 * b;
                cnt[b] += ((unsigned)(a0 >> sh) & 63u)
                        + ((unsigned)(a1 >> sh) & 63u)
                        + ((unsigned)(a2 >> sh) & 63u)
                        + ((unsigned)(a3 >> sh) & 63u);
            }
            a0 = a1 = a2 = a3 = 0ULL;
        }
    }

#pragma unroll
    for (int b = 0; b < NB_; b++) {
        unsigned tot = __reduce_add_sync(0xffffffffu, cnt[b]);
        if (lane == b) atomicAdd(out + c * NB_ + b, (float)tot);
    }
}

extern "C" void kernel_launch(void* const* d_in, const int* in_sizes, int n_in,
                              void* d_out, int out_size) {
    const float* x  = (const float*)d_in[0];
    const float* be = (const float*)d_in[1];
    const float* fr = (const float*)d_in[2];
    const float* bc = (const float*)d_in[3];
    float* out = (float*)d_out;

    static bool attr_done = false;
    if (!attr_done) {
        cudaFuncSetAttribute(hist_kernel,
                             cudaFuncAttributeMaxDynamicSharedMemorySize,
                             SMEM_TOTAL_);
        attr_done = true;
    }

    init_out_kernel<<<(out_size + 255) / 256, 256>>>(bc, out, out_size);
    hist_kernel<<<GRID_, THREADS_, SMEM_TOTAL_>>>(x, be, fr, out);
}

// round 8
// speedup vs baseline: 1.0122x; 1.0122x over previous
#include <cuda_runtime.h>
#include <cstdint>

// BinStats_27401891348536 fixed shapes:
// x: [64, 512, 28, 28] f32; bin_edges: [512, 11]; feature_ranges: [512];
// bin_counts: [512, 10]; out = bin_counts + per-channel histogram of x/range.
#define C_     512
#define NB_    10
#define NEDGE_ 11
#define NF4_   196            // 28*28/4 float4 per row
#define NWARP_ 3584           // 7*512 -> channel constant per warp; 24.2 blocks/SM
#define RFIX_  9              // 9*3584 = 32256 rows; remaining 512 rows: 32256+w
#define NCONTRIB_ 7           // warps per channel (3584/512)

// Zero-initialized device scratch; every run restores it to zero at the end,
// so graph replays are deterministic. No allocation APIs used.
__device__ float    g_scratch[C_ * NB_];
__device__ unsigned g_done[C_];

// searchsorted(inner, v, 'left') with uniform inner edges s_k = s0 + k*D:
// count of edges < x == clamp(ceil((x - s0)/D), 0, 9)
__device__ __forceinline__ unsigned long long bump(float x, float invD, float c0) {
    float u = fmaf(x, invD, c0);
    u = fminf(fmaxf(u, 0.0f), 9.0f);
    int b = __float2int_ru(u);
    return 1ULL << (6 * b);
}

// Streaming load with 256B L2 prefetch hint.
__device__ __forceinline__ float4 ldg_stream(const float4* p) {
    float4 v;
    asm volatile("ld.global.nc.L2::256B.v4.f32 {%0,%1,%2,%3}, [%4];"
                 : "=f"(v.x), "=f"(v.y), "=f"(v.z), "=f"(v.w) : "l"(p));
    return v;
}

__device__ __forceinline__ void load_row(float4 v[7], const float4* __restrict__ p,
                                         int lane, bool tail) {
    v[0] = ldg_stream(p +   0 + lane);
    v[1] = ldg_stream(p +  32 + lane);
    v[2] = ldg_stream(p +  64 + lane);
    v[3] = ldg_stream(p +  96 + lane);
    v[4] = ldg_stream(p + 128 + lane);
    v[5] = ldg_stream(p + 160 + lane);
    if (tail) v[6] = ldg_stream(p + 192 + lane);
}

__device__ __forceinline__ void acc_row(const float4 v[7], bool tail,
                                        unsigned long long& a0, unsigned long long& a1,
                                        unsigned long long& a2, unsigned long long& a3,
                                        float invD, float c0) {
#pragma unroll
    for (int i = 0; i < 6; i++) {
        a0 += bump(v[i].x, invD, c0);
        a1 += bump(v[i].y, invD, c0);
        a2 += bump(v[i].z, invD, c0);
        a3 += bump(v[i].w, invD, c0);
    }
    if (tail) {
        a0 += bump(v[6].x, invD, c0);
        a1 += bump(v[6].y, invD, c0);
        a2 += bump(v[6].z, invD, c0);
        a3 += bump(v[6].w, invD, c0);
    }
}

__device__ __forceinline__ void flush_acc(unsigned long long& a0, unsigned long long& a1,
                                          unsigned long long& a2, unsigned long long& a3,
                                          unsigned cnt[NB_]) {
#pragma unroll
    for (int b = 0; b < NB_; b++) {
        const int sh = 6 * b;
        cnt[b] += ((unsigned)(a0 >> sh) & 63u)
                + ((unsigned)(a1 >> sh) & 63u)
                + ((unsigned)(a2 >> sh) & 63u)
                + ((unsigned)(a3 >> sh) & 63u);
    }
    a0 = a1 = a2 = a3 = 0ULL;
}

__global__ void __launch_bounds__(32, 24) hist_kernel(
    const float4* __restrict__ x4,
    const float*  __restrict__ bin_edges,
    const float*  __restrict__ fr,
    const float*  __restrict__ bc,
    float*        __restrict__ out)
{
    const int lane = threadIdx.x;
    const int warp = blockIdx.x;
    const int c    = warp & (C_ - 1);
    const bool tail = (lane < 4);

    const float range = __ldg(&fr[c]);
    const float s0 = __ldg(&bin_edges[c * NEDGE_ + 1]) * range;
    const float s8 = __ldg(&bin_edges[c * NEDGE_ + 9]) * range;
    const float invD = 8.0f / (s8 - s0);
    const float c0   = -s0 * invD;

    const float4* base = x4 + (size_t)warp * NF4_;
    const size_t rstride = (size_t)NWARP_ * NF4_;

    unsigned long long a0 = 0, a1 = 0, a2 = 0, a3 = 0;
    unsigned cnt[NB_];
#pragma unroll
    for (int b = 0; b < NB_; b++) cnt[b] = 0;

    float4 A[7], B[7];
    load_row(A, base, lane, tail);

    // 9 rows, pipelined: prefetch row k+1 while binning row k.
    // Max increments per 6-bit field per acc = 9*7 = 63, exactly fits.
#pragma unroll
    for (int k = 0; k < RFIX_; k++) {
        if (k + 1 < RFIX_)
            load_row((k & 1) ? A : B, base + (size_t)(k + 1) * rstride, lane, tail);
        if (k & 1) acc_row(B, tail, a0, a1, a2, a3, invD, c0);
        else       acc_row(A, tail, a0, a1, a2, a3, invD, c0);
    }
    flush_acc(a0, a1, a2, a3, cnt);

    // Extra row for the first 512 warps (row 32256+warp, channel = warp).
    if (warp < C_) {
        load_row(A, x4 + (size_t)(RFIX_ * NWARP_ + warp) * NF4_, lane, tail);
        acc_row(A, tail, a0, a1, a2, a3, invD, c0);
        flush_acc(a0, a1, a2, a3, cnt);
    }

    // Warp totals -> scratch.
#pragma unroll
    for (int b = 0; b < NB_; b++) {
        unsigned tot = __reduce_add_sync(0xffffffffu, cnt[b]);
        if (lane == b) atomicAdd(&g_scratch[c * NB_ + b], (float)tot);
    }
    __threadfence();

    // Last contributor for this channel finalizes: out = bc + scratch, then
    // resets scratch/done to zero (restores the invariant for graph replay).
    unsigned old = 0;
    if (lane == 0) old = atomicAdd(&g_done[c], 1u);
    old = __shfl_sync(0xffffffffu, old, 0);
    if (old == NCONTRIB_ - 1) {
        __threadfence();
        if (lane < NB_) {
            const int i = c * NB_ + lane;
            float v = atomicAdd(&g_scratch[i], 0.0f);   // coherent read via L2
            out[i] = bc[i] + v;
            atomicExch(&g_scratch[i], 0.0f);
        }
        if (lane == 0) atomicExch(&g_done[c], 0u);
    }
}

extern "C" void kernel_launch(void* const* d_in, const int* in_sizes, int n_in,
                              void* d_out, int out_size) {
    const float* x  = (const float*)d_in[0];
    const float* be = (const float*)d_in[1];
    const float* fr = (const float*)d_in[2];
    const float* bc = (const float*)d_in[3];
    float* out = (float*)d_out;

    hist_kernel<<<NWARP_, 32>>>((const float4*)x, be, fr, bc, out);
}